// round 7
// baseline (speedup 1.0000x reference)
#include <cuda_runtime.h>

// Problem constants
#define BATCH 32
#define CH    64
#define HW    128
#define NK    4
#define TAPS  9          // 3x3
#define CIK   (CH*TAPS)  // 576

// Scratch (device globals: no allocation allowed)
// g_wmix layout: [b][ci][tap][co]  (co contiguous)
__device__ float g_wmix[BATCH * CH * TAPS * CH];   // 4.72 MB
__device__ float g_bmix[BATCH * CH];

// ---------------------------------------------------------------------------
// Kernel 1: mix weight bank + bias per sample
//   g_wmix[b][ci][tap][co] = sum_k att[b,k] * weight[k][co][ci][tap]
//   g_bmix[b][co]          = sum_k att[b,k] * bias[k][co]
// ---------------------------------------------------------------------------
__global__ void __launch_bounds__(256) mix_kernel(
    const float* __restrict__ att,     // [B, NK]
    const float* __restrict__ weight,  // [NK, C, C, 3, 3]
    const float* __restrict__ bias)    // [NK, C]
{
    int gid = blockIdx.x * 256 + threadIdx.x;
    const int TOT = BATCH * CH * TAPS * CH;  // 1,179,648
    if (gid < TOT) {
        int b    = gid / (CH * TAPS * CH);
        int rem  = gid - b * (CH * TAPS * CH);
        int ci   = rem / (TAPS * CH);
        int rem2 = rem - ci * (TAPS * CH);
        int tap  = rem2 >> 6;
        int co   = rem2 & 63;

        float a0 = att[b * NK + 0];
        float a1 = att[b * NK + 1];
        float a2 = att[b * NK + 2];
        float a3 = att[b * NK + 3];

        // weight index for k: (((k*CH + co)*CH + ci)*TAPS + tap)
        int base   = ((co * CH) + ci) * TAPS + tap;
        int stride = CH * CH * TAPS;
        float w = a0 * weight[base]
                + a1 * weight[base + stride]
                + a2 * weight[base + 2 * stride]
                + a3 * weight[base + 3 * stride];
        g_wmix[gid] = w;
    }
    if (gid < BATCH * CH) {
        int b  = gid >> 6;
        int co = gid & 63;
        float s = 0.f;
        #pragma unroll
        for (int k = 0; k < NK; k++)
            s += att[b * NK + k] * bias[k * CH + co];
        g_bmix[gid] = s;
    }
}

// ---------------------------------------------------------------------------
// Kernel 2: direct 3x3 conv, SAME padding, per-sample mixed weights.
// One CTA per (b, output row y). 256 threads.
// Thread (tx): c_out block = (tx>>4)*4 (4 channels), w block = (tx&15)*8.
// Accumulators: 4 co x 4 f32x2 pairs (8 w values) via fma.rn.f32x2 (FFMA2).
// ---------------------------------------------------------------------------

typedef unsigned long long u64;

__device__ __forceinline__ u64 ffma2(u64 d, u64 a, u64 b) {
    asm("fma.rn.f32x2 %0, %1, %2, %0;" : "+l"(d) : "l"(a), "l"(b));
    return d;
}
__device__ __forceinline__ u64 dup2(float v) {
    u64 p;
    asm("mov.b64 %0, {%1, %1};" : "=l"(p) : "f"(v));
    return p;
}

// Bank-conflict-avoiding index for the input row buffer: insert 2-float pad
// every 32 floats, so the 16 distinct 8-float-strided LDS.64 bases per warp
// land on distinct bank pairs (conflict-free).
#define XROW 144
__device__ __forceinline__ int XIDX(int c) { return c + ((c >> 5) << 1); }

__global__ void __launch_bounds__(256) conv_kernel(
    const float* __restrict__ x,   // [B, C, H, W]
    float* __restrict__ out)       // [B, C, H, W]
{
    __shared__ float xs[3 * XROW];         // 3 padded input rows (width 130 + pads)
    __shared__ u64   ws2[TAPS * CH];       // duplicated weight pairs, [tap][co]

    const int y  = blockIdx.x;   // 0..127
    const int b  = blockIdx.y;   // 0..31
    const int tx = threadIdx.x;

    const int co0 = (tx >> 4) << 2;  // 0..60 step 4
    const int w0  = (tx & 15) << 3;  // 0..120 step 8

    // Precomputed swizzled LDS offsets for the 5 even input pairs
    int xoff[5];
    #pragma unroll
    for (int j = 0; j < 5; j++) xoff[j] = XIDX(w0 + 2 * j);

    // Init accumulators with mixed bias
    u64 acc[4][4];
    #pragma unroll
    for (int i = 0; i < 4; i++) {
        u64 bp = dup2(g_bmix[b * CH + co0 + i]);
        #pragma unroll
        for (int j = 0; j < 4; j++) acc[i][j] = bp;
    }

    const float* xbase = x + (size_t)(b * CH) * HW * HW;
    const float* wbase = g_wmix + (size_t)(b * CH) * TAPS * CH;

    #pragma unroll 1
    for (int ci = 0; ci < CH; ci++) {
        __syncthreads();  // protect previous iteration's reads

        // --- stage input rows y-1..y+1 (padded width 130) ---
        const float* xc = xbase + ci * (HW * HW);
        for (int t = tx; t < 3 * 130; t += 256) {
            int r = t / 130;
            int c = t - 130 * r;
            int yy  = y - 1 + r;
            int col = c - 1;
            float v = 0.f;
            if ((unsigned)yy < HW && (unsigned)col < HW)
                v = xc[yy * HW + col];
            xs[r * XROW + XIDX(c)] = v;
        }
        // --- stage duplicated weight pairs for this ci (576 contiguous) ---
        const float* wc = wbase + ci * CIK;
        for (int t = tx; t < CIK; t += 256)
            ws2[t] = dup2(wc[t]);

        __syncthreads();

        // --- compute: 9 taps x (4 co x 4 pairs) FFMA2 ---
        #pragma unroll
        for (int ky = 0; ky < 3; ky++) {
            const float* xr = xs + ky * XROW;
            u64 xp[5];
            #pragma unroll
            for (int j = 0; j < 5; j++)
                xp[j] = *reinterpret_cast<const u64*>(xr + xoff[j]);
            u64 op[4];  // odd-aligned pairs for kx=1
            #pragma unroll
            for (int j = 0; j < 4; j++)
                op[j] = (xp[j] >> 32) | (xp[j + 1] << 32);

            #pragma unroll
            for (int kx = 0; kx < 3; kx++) {
                const u64* wrow = ws2 + (ky * 3 + kx) * CH + co0;  // warp-broadcast
                u64 wv0 = wrow[0], wv1 = wrow[1], wv2 = wrow[2], wv3 = wrow[3];
                const u64* bp = (kx == 0) ? xp : (kx == 1) ? op : (xp + 1);
                #pragma unroll
                for (int j = 0; j < 4; j++) {
                    acc[0][j] = ffma2(acc[0][j], wv0, bp[j]);
                    acc[1][j] = ffma2(acc[1][j], wv1, bp[j]);
                    acc[2][j] = ffma2(acc[2][j], wv2, bp[j]);
                    acc[3][j] = ffma2(acc[3][j], wv3, bp[j]);
                }
            }
        }
    }

    // --- store: 4 co x 8 contiguous w per thread, as 2x float4 per co ---
    union Cv { u64 u; float2 f; };
    #pragma unroll
    for (int i = 0; i < 4; i++) {
        float* o = out + (((size_t)(b * CH + co0 + i) * HW) + y) * HW + w0;
        Cv c0, c1, c2, c3;
        c0.u = acc[i][0]; c1.u = acc[i][1]; c2.u = acc[i][2]; c3.u = acc[i][3];
        float4 s0 = make_float4(c0.f.x, c0.f.y, c1.f.x, c1.f.y);
        float4 s1 = make_float4(c2.f.x, c2.f.y, c3.f.x, c3.f.y);
        *reinterpret_cast<float4*>(o)     = s0;
        *reinterpret_cast<float4*>(o + 4) = s1;
    }
}

// ---------------------------------------------------------------------------
// Launch. Inputs per metadata order: x, attention, weight, bias_p.
// ---------------------------------------------------------------------------
extern "C" void kernel_launch(void* const* d_in, const int* in_sizes, int n_in,
                              void* d_out, int out_size)
{
    const float* x    = (const float*)d_in[0];  // [32,64,128,128]
    const float* att  = (const float*)d_in[1];  // [32,4]
    const float* wgt  = (const float*)d_in[2];  // [4,64,64,3,3]
    const float* bias = (const float*)d_in[3];  // [4,64]
    float* out = (float*)d_out;

    const int TOT = BATCH * CH * TAPS * CH;
    mix_kernel<<<(TOT + 255) / 256, 256>>>(att, wgt, bias);

    dim3 grid(HW, BATCH);  // (y, b)
    conv_kernel<<<grid, 256>>>(x, out);
}

// round 8
// speedup vs baseline: 1.3466x; 1.3466x over previous
#include <cuda_runtime.h>

// Problem constants
#define BATCH 32
#define CH    64
#define HW    128
#define CHW   (HW*HW)
#define NK    4
#define TAPS  9          // 3x3
#define CIK   (CH*TAPS)  // 576

// Scratch (device globals: no allocation allowed)
// g_wmix layout: [b][ci][tap][co]  (co contiguous)
__device__ float g_wmix[BATCH * CH * TAPS * CH];   // 4.72 MB
__device__ float g_bmix[BATCH * CH];

// ---------------------------------------------------------------------------
// Kernel 1: mix weight bank + bias per sample
// ---------------------------------------------------------------------------
__global__ void __launch_bounds__(256) mix_kernel(
    const float* __restrict__ att,     // [B, NK]
    const float* __restrict__ weight,  // [NK, C, C, 3, 3]
    const float* __restrict__ bias)    // [NK, C]
{
    int gid = blockIdx.x * 256 + threadIdx.x;
    const int TOT = BATCH * CH * TAPS * CH;  // 1,179,648
    if (gid < TOT) {
        int b    = gid / (CH * TAPS * CH);
        int rem  = gid - b * (CH * TAPS * CH);
        int ci   = rem / (TAPS * CH);
        int rem2 = rem - ci * (TAPS * CH);
        int tap  = rem2 >> 6;
        int co   = rem2 & 63;

        float a0 = att[b * NK + 0];
        float a1 = att[b * NK + 1];
        float a2 = att[b * NK + 2];
        float a3 = att[b * NK + 3];

        int base   = ((co * CH) + ci) * TAPS + tap;
        int stride = CH * CH * TAPS;
        float w = a0 * weight[base]
                + a1 * weight[base + stride]
                + a2 * weight[base + 2 * stride]
                + a3 * weight[base + 3 * stride];
        g_wmix[gid] = w;
    }
    if (gid < BATCH * CH) {
        int b  = gid >> 6;
        int co = gid & 63;
        float s = 0.f;
        #pragma unroll
        for (int k = 0; k < NK; k++)
            s += att[b * NK + k] * bias[k * CH + co];
        g_bmix[gid] = s;
    }
}

// ---------------------------------------------------------------------------
// Kernel 2: direct 3x3 conv, double-buffered staging, FFMA2 compute.
// One CTA per (b, output row y). 256 threads.
// Thread: 4 c_out x 8 w (4 f32x2 pairs). 144 FFMA2 per c_in per thread.
// ---------------------------------------------------------------------------

typedef unsigned long long u64;

__device__ __forceinline__ u64 ffma2(u64 d, u64 a, u64 b) {
    asm("fma.rn.f32x2 %0, %1, %2, %0;" : "+l"(d) : "l"(a), "l"(b));
    return d;
}
__device__ __forceinline__ u64 dup2(float v) {
    u64 p;
    asm("mov.b64 %0, {%1, %1};" : "=l"(p) : "f"(v));
    return p;
}
__device__ __forceinline__ u64 pack2(unsigned lo, unsigned hi) {
    u64 p;
    asm("mov.b64 %0, {%1, %2};" : "=l"(p) : "r"(lo), "r"(hi));
    return p;
}

// Bank-conflict-avoiding index: 2-float pad every 32 floats.
#define XROW 144
__device__ __forceinline__ int XIDX(int c) { return c + ((c >> 5) << 1); }

__global__ void __launch_bounds__(256) conv_kernel(
    const float* __restrict__ x,   // [B, C, H, W]
    float* __restrict__ out)       // [B, C, H, W]
{
    __shared__ float xs[2][3 * XROW];                    // input rows, double-buffered
    __shared__ alignas(16) u64 ws2[2][CIK];              // dup'd weight pairs [tap][co]

    const int y  = blockIdx.x;   // 0..127
    const int b  = blockIdx.y;   // 0..31
    const int tx = threadIdx.x;

    const int co0 = (tx >> 4) << 2;  // 0..60 step 4
    const int w0  = (tx & 15) << 3;  // 0..120 step 8

    // Swizzled LDS offsets for the 5 even input pairs (loop-invariant)
    int xoff[5];
    #pragma unroll
    for (int j = 0; j < 5; j++) xoff[j] = XIDX(w0 + 2 * j);

    // ---- per-thread staging map (loop-invariant) ----
    // input rows: 3 x 130 = 390 slots; slot0 = tx, slot1 = tx+256 (if <390)
    const int t0 = tx, t1 = tx + 256;
    const int r0 = t0 / 130, c0 = t0 - 130 * r0;
    const int r1 = t1 / 130, c1 = t1 - 130 * r1;
    const bool a1 = (t1 < 390);
    const int yy0 = y - 1 + r0, col0 = c0 - 1;
    const int yy1 = y - 1 + r1, col1 = c1 - 1;
    const bool v0 = ((unsigned)yy0 < HW) && ((unsigned)col0 < HW);
    const bool v1 = a1 && ((unsigned)yy1 < HW) && ((unsigned)col1 < HW);
    const int gox0 = yy0 * HW + col0;
    const int gox1 = yy1 * HW + col1;
    const int sox0 = r0 * XROW + XIDX(c0);
    const int sox1 = r1 * XROW + XIDX(c1);
    // weights: 576 slots; tx, tx+256 always; tx+512 if tx<64
    const bool aw2 = (tx < 64);

    // Init accumulators with mixed bias
    u64 acc[4][4];
    #pragma unroll
    for (int i = 0; i < 4; i++) {
        u64 bp = dup2(g_bmix[b * CH + co0 + i]);
        #pragma unroll
        for (int j = 0; j < 4; j++) acc[i][j] = bp;
    }

    const float* xbase = x + (size_t)(b * CH) * CHW;
    const float* wbase = g_wmix + (size_t)(b * CH) * TAPS * CH;

    // ---- prologue: stage ci = 0 into buffer 0 ----
    {
        const float* xc = xbase;
        xs[0][sox0] = v0 ? xc[gox0] : 0.f;
        if (a1) xs[0][sox1] = v1 ? xc[gox1] : 0.f;
        const float* wc = wbase;
        ws2[0][t0] = dup2(wc[t0]);
        ws2[0][t1] = dup2(wc[t1]);
        if (aw2) ws2[0][tx + 512] = dup2(wc[tx + 512]);
    }
    __syncthreads();

    #pragma unroll 1
    for (int ci = 0; ci < CH; ci++) {
        const int p = ci & 1;

        // --- prefetch ci+1 from global (latency hidden by compute) ---
        float pi0 = 0.f, pi1 = 0.f, pw0 = 0.f, pw1 = 0.f, pw2 = 0.f;
        if (ci + 1 < CH) {
            const float* xc = xbase + (ci + 1) * CHW;
            pi0 = v0 ? __ldg(xc + gox0) : 0.f;
            pi1 = v1 ? __ldg(xc + gox1) : 0.f;
            const float* wc = wbase + (ci + 1) * CIK;
            pw0 = __ldg(wc + t0);
            pw1 = __ldg(wc + t1);
            if (aw2) pw2 = __ldg(wc + tx + 512);
        }

        // --- compute from buffer p: 9 taps x (4 co x 4 pairs) FFMA2 ---
        const u64* wsp = ws2[p];
        #pragma unroll
        for (int ky = 0; ky < 3; ky++) {
            const float* xr = xs[p] + ky * XROW;
            uint2 xq[5];
            #pragma unroll
            for (int j = 0; j < 5; j++)
                xq[j] = *reinterpret_cast<const uint2*>(xr + xoff[j]);
            u64 ep[5], op[4];
            #pragma unroll
            for (int j = 0; j < 5; j++) ep[j] = pack2(xq[j].x, xq[j].y);
            #pragma unroll
            for (int j = 0; j < 4; j++) op[j] = pack2(xq[j].y, xq[j + 1].x);

            #pragma unroll
            for (int kx = 0; kx < 3; kx++) {
                const u64* wrow = wsp + (ky * 3 + kx) * CH + co0;
                ulonglong2 wa = *reinterpret_cast<const ulonglong2*>(wrow);
                ulonglong2 wb = *reinterpret_cast<const ulonglong2*>(wrow + 2);
                const u64* bp = (kx == 0) ? ep : (kx == 1) ? op : (ep + 1);
                #pragma unroll
                for (int j = 0; j < 4; j++) {
                    acc[0][j] = ffma2(acc[0][j], wa.x, bp[j]);
                    acc[1][j] = ffma2(acc[1][j], wa.y, bp[j]);
                    acc[2][j] = ffma2(acc[2][j], wb.x, bp[j]);
                    acc[3][j] = ffma2(acc[3][j], wb.y, bp[j]);
                }
            }
        }

        // --- store prefetch into the other buffer ---
        if (ci + 1 < CH) {
            float* xd = xs[p ^ 1];
            xd[sox0] = pi0;
            if (a1) xd[sox1] = pi1;
            u64* wd = ws2[p ^ 1];
            wd[t0] = dup2(pw0);
            wd[t1] = dup2(pw1);
            if (aw2) wd[tx + 512] = dup2(pw2);
        }
        __syncthreads();
    }

    // --- store: 4 co x 8 contiguous w per thread ---
    union Cv { u64 u; float2 f; };
    #pragma unroll
    for (int i = 0; i < 4; i++) {
        float* o = out + (((size_t)(b * CH + co0 + i) * HW) + y) * HW + w0;
        Cv q0, q1, q2, q3;
        q0.u = acc[i][0]; q1.u = acc[i][1]; q2.u = acc[i][2]; q3.u = acc[i][3];
        float4 s0 = make_float4(q0.f.x, q0.f.y, q1.f.x, q1.f.y);
        float4 s1 = make_float4(q2.f.x, q2.f.y, q3.f.x, q3.f.y);
        *reinterpret_cast<float4*>(o)     = s0;
        *reinterpret_cast<float4*>(o + 4) = s1;
    }
}

// ---------------------------------------------------------------------------
// Launch. Inputs: x, attention, weight, bias_p.
// ---------------------------------------------------------------------------
extern "C" void kernel_launch(void* const* d_in, const int* in_sizes, int n_in,
                              void* d_out, int out_size)
{
    const float* x    = (const float*)d_in[0];  // [32,64,128,128]
    const float* att  = (const float*)d_in[1];  // [32,4]
    const float* wgt  = (const float*)d_in[2];  // [4,64,64,3,3]
    const float* bias = (const float*)d_in[3];  // [4,64]
    float* out = (float*)d_out;

    const int TOT = BATCH * CH * TAPS * CH;
    mix_kernel<<<(TOT + 255) / 256, 256>>>(att, wgt, bias);

    dim3 grid(HW, BATCH);  // (y, b)
    conv_kernel<<<grid, 256>>>(x, out);
}

// round 9
// speedup vs baseline: 1.6074x; 1.1937x over previous
#include <cuda_runtime.h>

// Problem constants
#define BATCH 32
#define CH    64
#define HW    128
#define CHW   (HW*HW)
#define NK    4
#define TAPS  9
#define CIK   (CH*TAPS)        // 576
#define CI_CHUNK 4
#define NCHUNK  (CH/CI_CHUNK)  // 16
#define WCHUNK  (CI_CHUNK*CIK) // 2304 floats per weight chunk
#define ISLOT   (CI_CHUNK*3*130) // 1560 input staging slots per chunk

// Scratch (device globals: no allocation allowed)
// g_wmix layout: [b][ci][tap][co]  (co contiguous)
__device__ float g_wmix[BATCH * CH * TAPS * CH];
__device__ float g_bmix[BATCH * CH];

// ---------------------------------------------------------------------------
// Kernel 1: mix weight bank + bias per sample
// ---------------------------------------------------------------------------
__global__ void __launch_bounds__(256) mix_kernel(
    const float* __restrict__ att,     // [B, NK]
    const float* __restrict__ weight,  // [NK, C, C, 3, 3]
    const float* __restrict__ bias)    // [NK, C]
{
    int gid = blockIdx.x * 256 + threadIdx.x;
    const int TOT = BATCH * CH * TAPS * CH;
    if (gid < TOT) {
        int b    = gid / (CH * TAPS * CH);
        int rem  = gid - b * (CH * TAPS * CH);
        int ci   = rem / (TAPS * CH);
        int rem2 = rem - ci * (TAPS * CH);
        int tap  = rem2 >> 6;
        int co   = rem2 & 63;

        float a0 = att[b * NK + 0];
        float a1 = att[b * NK + 1];
        float a2 = att[b * NK + 2];
        float a3 = att[b * NK + 3];

        int base   = ((co * CH) + ci) * TAPS + tap;
        int stride = CH * CH * TAPS;
        g_wmix[gid] = a0 * weight[base]
                    + a1 * weight[base + stride]
                    + a2 * weight[base + 2 * stride]
                    + a3 * weight[base + 3 * stride];
    }
    if (gid < BATCH * CH) {
        int b  = gid >> 6;
        int co = gid & 63;
        float s = 0.f;
        #pragma unroll
        for (int k = 0; k < NK; k++)
            s += att[b * NK + k] * bias[k * CH + co];
        g_bmix[gid] = s;
    }
}

// ---------------------------------------------------------------------------
// Kernel 2: direct 3x3 conv, FFMA2 paired over c_out.
// One CTA per (b, y). 256 threads: co0 = (tx>>4)*4 (2 co-pairs), w0 = (tx&15)*8.
// Inputs stored DUPLICATED (u64 = {v,v}) in smem: tap windows are aligned
// LDS.128, zero pack MOVs. Weight pairs load directly as adjacent floats
// (warp-broadcast LDS.128). 4-ci chunks, double-buffered, 1 barrier/chunk.
// ---------------------------------------------------------------------------

typedef unsigned long long u64;

__device__ __forceinline__ u64 ffma2(u64 d, u64 a, u64 b) {
    asm("fma.rn.f32x2 %0, %1, %2, %0;" : "+l"(d) : "l"(a), "l"(b));
    return d;
}
__device__ __forceinline__ u64 dup2(float v) {
    u64 p;
    asm("mov.b64 %0, {%1, %1};" : "=l"(p) : "f"(v));
    return p;
}

// Padded u64 row: 2-slot pad every 16 → 2-way max on strided LDS.128.
#define XU 148
__device__ __forceinline__ int DIDX(int j) { return j + ((j >> 4) << 1); }

__global__ void __launch_bounds__(256, 2) conv_kernel(
    const float* __restrict__ x,   // [B, C, H, W]
    float* __restrict__ out)       // [B, C, H, W]
{
    __shared__ alignas(16) u64   xdup[2][CI_CHUNK * 3 * XU];  // dup'd input rows
    __shared__ alignas(16) float wsf[2][WCHUNK];              // plain mixed weights

    const int y  = blockIdx.x;
    const int b  = blockIdx.y;
    const int tx = threadIdx.x;

    const int co0 = (tx >> 4) << 2;  // 0..60 step 4
    const int w0  = (tx & 15) << 3;  // 0..120 step 8

    // LDS offsets for the 5 input .128 loads (u64 idx, 16B aligned)
    int xoff[5];
    #pragma unroll
    for (int i = 0; i < 5; i++) xoff[i] = DIDX(w0 + 2 * i);

    // ---- input staging map: 7 slots per thread (last guarded) ----
    int  gofs[7], sofs[7];
    bool val[7], act[7];
    #pragma unroll
    for (int k = 0; k < 7; k++) {
        int s = tx + k * 256;
        act[k] = (s < ISLOT);
        int ss = act[k] ? s : 0;
        int ci4 = ss / 390;
        int rem = ss - 390 * ci4;
        int r   = rem / 130;
        int c   = rem - 130 * r;
        int yy  = y - 1 + r;
        int col = c - 1;
        val[k]  = act[k] && ((unsigned)yy < HW) && ((unsigned)col < HW);
        gofs[k] = ci4 * CHW + yy * HW + col;
        sofs[k] = (ci4 * 3 + r) * XU + DIDX(c);
    }

    // Init accumulators with mixed bias: pair = (bmix[co], bmix[co+1])
    u64 acc[2][8];
    #pragma unroll
    for (int cp = 0; cp < 2; cp++) {
        u64 bp = *reinterpret_cast<const u64*>(g_bmix + b * CH + co0 + 2 * cp);
        #pragma unroll
        for (int wi = 0; wi < 8; wi++) acc[cp][wi] = bp;
    }

    const float* xbase = x + (size_t)(b * CH) * CHW;
    const float* wbase = g_wmix + (size_t)(b * CH) * TAPS * CH;

    // ---- prologue: stage chunk 0 into buffer 0 ----
    {
        #pragma unroll
        for (int k = 0; k < 7; k++)
            if (act[k]) xdup[0][sofs[k]] = dup2(val[k] ? __ldg(xbase + gofs[k]) : 0.f);
        #pragma unroll
        for (int k = 0; k < 9; k++)
            wsf[0][tx + k * 256] = __ldg(wbase + tx + k * 256);
    }
    __syncthreads();

    #pragma unroll 1
    for (int chunk = 0; chunk < NCHUNK; chunk++) {
        const int p = chunk & 1;

        // --- prefetch next chunk into registers ---
        float pin[7], pwt[9];
        if (chunk + 1 < NCHUNK) {
            const float* xc = xbase + (chunk + 1) * CI_CHUNK * CHW;
            #pragma unroll
            for (int k = 0; k < 7; k++)
                pin[k] = val[k] ? __ldg(xc + gofs[k]) : 0.f;
            const float* wc = wbase + (chunk + 1) * WCHUNK;
            #pragma unroll
            for (int k = 0; k < 9; k++)
                pwt[k] = __ldg(wc + tx + k * 256);
        }

        // --- compute 4 ci from buffer p ---
        #pragma unroll
        for (int ci4 = 0; ci4 < CI_CHUNK; ci4++) {
            const float* wr = wsf[p] + ci4 * CIK;
            const u64*   xb = xdup[p] + ci4 * 3 * XU;
            #pragma unroll
            for (int ky = 0; ky < 3; ky++) {
                const u64* xr = xb + ky * XU;
                u64 xw[10];
                #pragma unroll
                for (int i = 0; i < 5; i++) {
                    ulonglong2 q = *reinterpret_cast<const ulonglong2*>(xr + xoff[i]);
                    xw[2 * i] = q.x; xw[2 * i + 1] = q.y;
                }
                #pragma unroll
                for (int kx = 0; kx < 3; kx++) {
                    ulonglong2 wv = *reinterpret_cast<const ulonglong2*>(
                        wr + (ky * 3 + kx) * CH + co0);  // warp-broadcast
                    #pragma unroll
                    for (int wi = 0; wi < 8; wi++) {
                        acc[0][wi] = ffma2(acc[0][wi], wv.x, xw[kx + wi]);
                        acc[1][wi] = ffma2(acc[1][wi], wv.y, xw[kx + wi]);
                    }
                }
            }
        }

        // --- store prefetch into the other buffer ---
        if (chunk + 1 < NCHUNK) {
            u64*   xd = xdup[p ^ 1];
            float* wd = wsf[p ^ 1];
            #pragma unroll
            for (int k = 0; k < 7; k++)
                if (act[k]) xd[sofs[k]] = dup2(pin[k]);
            #pragma unroll
            for (int k = 0; k < 9; k++)
                wd[tx + k * 256] = pwt[k];
        }
        __syncthreads();
    }

    // --- stores: split each co-pair, 2x STG.128 per co ---
    union Cv { u64 u; float2 f; };
    #pragma unroll
    for (int cp = 0; cp < 2; cp++) {
        Cv v[8];
        #pragma unroll
        for (int wi = 0; wi < 8; wi++) v[wi].u = acc[cp][wi];
        #pragma unroll
        for (int half = 0; half < 2; half++) {
            int co = co0 + 2 * cp + half;
            float* o = out + (((size_t)(b * CH + co) * HW) + y) * HW + w0;
            float4 s0, s1;
            if (half == 0) {
                s0 = make_float4(v[0].f.x, v[1].f.x, v[2].f.x, v[3].f.x);
                s1 = make_float4(v[4].f.x, v[5].f.x, v[6].f.x, v[7].f.x);
            } else {
                s0 = make_float4(v[0].f.y, v[1].f.y, v[2].f.y, v[3].f.y);
                s1 = make_float4(v[4].f.y, v[5].f.y, v[6].f.y, v[7].f.y);
            }
            *reinterpret_cast<float4*>(o)     = s0;
            *reinterpret_cast<float4*>(o + 4) = s1;
        }
    }
}

// ---------------------------------------------------------------------------
// Launch. Inputs: x, attention, weight, bias_p.
// ---------------------------------------------------------------------------
extern "C" void kernel_launch(void* const* d_in, const int* in_sizes, int n_in,
                              void* d_out, int out_size)
{
    const float* x    = (const float*)d_in[0];  // [32,64,128,128]
    const float* att  = (const float*)d_in[1];  // [32,4]
    const float* wgt  = (const float*)d_in[2];  // [4,64,64,3,3]
    const float* bias = (const float*)d_in[3];  // [4,64]
    float* out = (float*)d_out;

    const int TOT = BATCH * CH * TAPS * CH;
    mix_kernel<<<(TOT + 255) / 256, 256>>>(att, wgt, bias);

    dim3 grid(HW, BATCH);  // (y, b)
    conv_kernel<<<grid, 256>>>(x, out);
}